// round 6
// baseline (speedup 1.0000x reference)
#include <cuda_runtime.h>
#include <cuda_bf16.h>
#include <math.h>
#include <stdint.h>

#define Bsz 32
#define Pn  196
#define Dn  2048
#define Hn  512
#define Vn  30000
#define Tn  19
#define Vp  30080
#define Mrows 608
#define Mp  640
#define NCTA 148

// ---------------- fp32 scratch ----------------
__device__ float g_avg[Bsz * Dn];
__device__ float g_h[Bsz * Hn];
__device__ float g_c[Bsz * Hn];
__device__ float g_hall[Tn * Bsz * Hn];
__device__ float g_att_img[Bsz * Pn * Hn];
__device__ float g_emb[Bsz * Tn * Hn];           // rows = b*19+t
__device__ float g_embW[Bsz * Tn * 4 * Hn];
__device__ float g_hproj[Bsz * Hn];
__device__ float g_gate[Bsz * Dn];               // sigmoid applied
__device__ float g_e[Bsz * Pn];
__device__ float g_xc[Bsz * Dn];
__device__ float g_pa[2 * Bsz * 4 * Hn];
__device__ float g_pb[Bsz * 4 * Hn];
__device__ float g_pi_h[8 * Bsz * Hn];
__device__ float g_pi_c[8 * Bsz * Hn];
// barrier state
__device__ int          g_barcnt;
__device__ volatile int g_bargen;

// ---------------- bf16 split scratch ----------------
__device__ __nv_bfloat16 g_img_hi[Bsz * Pn * Dn];
__device__ __nv_bfloat16 g_img_lo[Bsz * Pn * Dn];
__device__ __nv_bfloat16 g_watt_hi[Hn * Dn];
__device__ __nv_bfloat16 g_watt_lo[Hn * Dn];
__device__ __nv_bfloat16 g_wout_hi[Vp * Hn];
__device__ __nv_bfloat16 g_wout_lo[Vp * Hn];
__device__ __nv_bfloat16 g_wih_hi[4 * Hn * Hn];
__device__ __nv_bfloat16 g_wih_lo[4 * Hn * Hn];
__device__ __nv_bfloat16 g_embh[Mp * Hn];
__device__ __nv_bfloat16 g_embl[Mp * Hn];
__device__ __nv_bfloat16 g_hallh[Mp * Hn];
__device__ __nv_bfloat16 g_halll[Mp * Hn];

__device__ __forceinline__ float sigf(float x) { return 1.f / (1.f + expf(-x)); }

__device__ __forceinline__ uint32_t smem_u32(const void* p) {
    uint32_t a;
    asm("{ .reg .u64 t; cvta.to.shared.u64 t, %1; cvt.u32.u64 %0, t; }" : "=r"(a) : "l"(p));
    return a;
}
__device__ __forceinline__ void ldmx4(uint32_t* r, uint32_t addr) {
    asm volatile("ldmatrix.sync.aligned.m8n8.x4.shared.b16 {%0,%1,%2,%3}, [%4];"
                 : "=r"(r[0]), "=r"(r[1]), "=r"(r[2]), "=r"(r[3]) : "r"(addr));
}
__device__ __forceinline__ void mma16816(float* d, const uint32_t* a, const uint32_t* b) {
    asm volatile(
        "mma.sync.aligned.m16n8k16.row.col.f32.bf16.bf16.f32 "
        "{%0,%1,%2,%3}, {%4,%5,%6,%7}, {%8,%9}, {%0,%1,%2,%3};"
        : "+f"(d[0]), "+f"(d[1]), "+f"(d[2]), "+f"(d[3])
        : "r"(a[0]), "r"(a[1]), "r"(a[2]), "r"(a[3]), "r"(b[0]), "r"(b[1]));
}
#define CP16(s, g)  asm volatile("cp.async.cg.shared.global [%0], [%1], 16;" :: "r"(s), "l"(g))
#define CPCOMMIT()  asm volatile("cp.async.commit_group;" ::: "memory")
#define CPWAIT1()   asm volatile("cp.async.wait_group 1;" ::: "memory")
#define CPWAIT0()   asm volatile("cp.async.wait_group 0;" ::: "memory")

// ==================== split-bf16 HMMA GEMM: 2-stage, 2 CTAs/SM ====================
#define RSB 80
#define TSZ (128 * RSB)
#define STG (4 * TSZ)
#define HMMA_SMEM (2 * STG)      // 81920

template <int OUTMAP>
__global__ __launch_bounds__(256, 2)
void hmma_gemm(const __nv_bfloat16* __restrict__ Ahi, const __nv_bfloat16* __restrict__ Alo,
               const __nv_bfloat16* __restrict__ Bhi, const __nv_bfloat16* __restrict__ Blo,
               const float* __restrict__ bias, float* __restrict__ C,
               int M, int N, int K, int ldc)
{
    extern __shared__ char smc[];
    const uint32_t sb = smem_u32(smc);
    const int tid = threadIdx.x;
    const int lane = tid & 31, wid = tid >> 5;
    const int wm = wid & 1, wn = wid >> 1;
    const int m0 = blockIdx.y * 128, n0 = blockIdx.x * 128;

    int r0 = tid >> 2, c0 = tid & 3;
    int r1 = (tid + 256) >> 2, c1 = tid & 3;
    const __nv_bfloat16* base0[4] = {
        Ahi + (size_t)(m0 + r0) * K + c0 * 8,
        Alo + (size_t)(m0 + r0) * K + c0 * 8,
        Bhi + (size_t)(n0 + r0) * K + c0 * 8,
        Blo + (size_t)(n0 + r0) * K + c0 * 8 };
    const __nv_bfloat16* base1[4] = {
        Ahi + (size_t)(m0 + r1) * K + c1 * 8,
        Alo + (size_t)(m0 + r1) * K + c1 * 8,
        Bhi + (size_t)(n0 + r1) * K + c1 * 8,
        Blo + (size_t)(n0 + r1) * K + c1 * 8 };
    const uint32_t so0 = (uint32_t)(r0 * RSB + c0 * 16);
    const uint32_t so1 = (uint32_t)(r1 * RSB + c1 * 16);

    const int arow = (lane & 7) | (((lane >> 3) & 1) << 3);
    const int akh  = lane >> 4;
    const int brow = (lane & 7) + ((lane >> 4) << 3);
    const int bkh  = (lane >> 3) & 1;

    float acc[4][4][4];
#pragma unroll
    for (int i = 0; i < 4; i++)
#pragma unroll
        for (int j = 0; j < 4; j++)
#pragma unroll
            for (int e = 0; e < 4; e++) acc[i][j][e] = 0.f;

    const int nit = K / 32;

    // prologue: stages 0,1
#pragma unroll
    for (int pi = 0; pi < 2; pi++) {
        uint32_t dst = sb + pi * STG;
        int kof = pi * 32;
#pragma unroll
        for (int tno = 0; tno < 4; tno++) {
            CP16(dst + tno * TSZ + so0, base0[tno] + kof);
            CP16(dst + tno * TSZ + so1, base1[tno] + kof);
        }
        CPCOMMIT();
    }

    for (int it = 0; it < nit; it++) {
        if (it + 1 < nit) { CPWAIT1(); } else { CPWAIT0(); }
        __syncthreads();

        const uint32_t stb = sb + (it & 1) * STG;
#pragma unroll
        for (int ks = 0; ks < 2; ks++) {
            uint32_t ah[4][4], al[4][4], bh[4][2], bl[4][2];
#pragma unroll
            for (int mt = 0; mt < 4; mt++) {
                uint32_t ra = (uint32_t)((wm * 64 + mt * 16 + arow) * RSB + ks * 32 + akh * 16);
                ldmx4(ah[mt], stb + 0 * TSZ + ra);
                ldmx4(al[mt], stb + 1 * TSZ + ra);
            }
#pragma unroll
            for (int g = 0; g < 2; g++) {
                uint32_t rb = (uint32_t)((wn * 32 + g * 16 + brow) * RSB + ks * 32 + bkh * 16);
                uint32_t t0[4], t1[4];
                ldmx4(t0, stb + 2 * TSZ + rb);
                ldmx4(t1, stb + 3 * TSZ + rb);
                bh[g * 2][0] = t0[0]; bh[g * 2][1] = t0[1];
                bh[g * 2 + 1][0] = t0[2]; bh[g * 2 + 1][1] = t0[3];
                bl[g * 2][0] = t1[0]; bl[g * 2][1] = t1[1];
                bl[g * 2 + 1][0] = t1[2]; bl[g * 2 + 1][1] = t1[3];
            }
#pragma unroll
            for (int mt = 0; mt < 4; mt++)
#pragma unroll
                for (int nt = 0; nt < 4; nt++) {
                    mma16816(acc[mt][nt], ah[mt], bh[nt]);
                    mma16816(acc[mt][nt], ah[mt], bl[nt]);
                    mma16816(acc[mt][nt], al[mt], bh[nt]);
                }
        }
        __syncthreads();

        if (it + 2 < nit) {
            uint32_t dst = sb + (it & 1) * STG;
            int kof = (it + 2) * 32;
#pragma unroll
            for (int tno = 0; tno < 4; tno++) {
                CP16(dst + tno * TSZ + so0, base0[tno] + kof);
                CP16(dst + tno * TSZ + so1, base1[tno] + kof);
            }
            CPCOMMIT();
        }
    }

#pragma unroll
    for (int mt = 0; mt < 4; mt++) {
#pragma unroll
        for (int half = 0; half < 2; half++) {
            int r = m0 + wm * 64 + mt * 16 + (lane >> 2) + half * 8;
            bool rowok; float* Crow;
            if (OUTMAP) {
                int ob = r & 31, ot = r >> 5;
                rowok = (ot < Tn);
                Crow = C + (size_t)(ob * Tn + ot) * ldc;
            } else {
                rowok = (r < M);
                Crow = C + (size_t)r * ldc;
            }
            if (!rowok) continue;
#pragma unroll
            for (int nt = 0; nt < 4; nt++) {
                int n = n0 + wn * 32 + nt * 8 + (lane & 3) * 2;
                if (n + 1 < N) {
                    float v0 = acc[mt][nt][half * 2 + 0];
                    float v1 = acc[mt][nt][half * 2 + 1];
                    if (bias) { v0 += bias[n]; v1 += bias[n + 1]; }
                    *(float2*)(Crow + n) = make_float2(v0, v1);
                } else if (n < N) {
                    float v0 = acc[mt][nt][half * 2 + 0];
                    if (bias) v0 += bias[n];
                    Crow[n] = v0;
                }
            }
        }
    }
}

// ==================== conversions ====================
__global__ void conv_split(const float* __restrict__ src, __nv_bfloat16* __restrict__ hi,
                           __nv_bfloat16* __restrict__ lo, int M, int K, int Mpad)
{
    int idx = blockIdx.x * 256 + threadIdx.x;
    if (idx >= Mpad * K) return;
    int r = idx / K;
    float v = (r < M) ? src[idx] : 0.f;
    __nv_bfloat16 h = __float2bfloat16(v);
    hi[idx] = h;
    lo[idx] = __float2bfloat16(v - __bfloat162float(h));
}

__global__ void conv_splitT(const float* __restrict__ src, int ldsrc,
                            __nv_bfloat16* __restrict__ hi, __nv_bfloat16* __restrict__ lo,
                            int K, int N, int Npad)
{
    __shared__ float tile[32][33];
    int n0 = blockIdx.x * 32, k0 = blockIdx.y * 32;
    int tx = threadIdx.x, ty = threadIdx.y;
#pragma unroll
    for (int i = 0; i < 32; i += 8) {
        int n = n0 + tx;
        tile[ty + i][tx] = (n < N) ? src[(size_t)(k0 + ty + i) * ldsrc + n] : 0.f;
    }
    __syncthreads();
#pragma unroll
    for (int i = 0; i < 32; i += 8) {
        int n = n0 + ty + i, k = k0 + tx;
        if (n < Npad) {
            float v = tile[tx][ty + i];
            __nv_bfloat16 h = __float2bfloat16(v);
            hi[(size_t)n * K + k] = h;
            lo[(size_t)n * K + k] = __float2bfloat16(v - __bfloat162float(h));
        }
    }
}

__global__ void pad_hall_kernel()
{
    int idx = blockIdx.x * 256 + threadIdx.x;
    if (idx >= (Mp - Mrows) * Hn) return;
    g_hallh[Mrows * Hn + idx] = __float2bfloat16(0.f);
    g_halll[Mrows * Hn + idx] = __float2bfloat16(0.f);
}

// ==================== init-only small GEMM (split-K) ====================
__global__ __launch_bounds__(64)
void gemm_pass(const float* A0, int lda0, const float* B0, int ldb0, float* P0, int N0, int K0, int ks0, int nt0,
               const float* A1, int lda1, const float* B1, int ldb1, float* P1, int N1, int K1, int ks1, int nt1)
{
    const float* A; const float* B; float* P;
    int N, K, ks, nt, lda, ldb;
    int id = blockIdx.x;
    int blocks0 = nt0 * ks0;
    if (id < blocks0) { A=A0; B=B0; P=P0; N=N0; K=K0; ks=ks0; nt=nt0; lda=lda0; ldb=ldb0; }
    else { id -= blocks0; A=A1; B=B1; P=P1; N=N1; K=K1; ks=ks1; nt=nt1; lda=lda1; ldb=ldb1; }

    int ntile = id % nt;
    int ksi   = id / nt;
    int kLen  = K / ks;
    int kbeg  = ksi * kLen, kend = kbeg + kLen;
    int n0    = ntile * 32;

    __shared__ float As[32][36];
    __shared__ float Bs[32][32];
    const int tid = threadIdx.x;
    const int tx = tid & 7, ty = tid >> 3;
    const int lrow = tid >> 3, lc4 = tid & 7;

    float acc[4][4];
#pragma unroll
    for (int i = 0; i < 4; i++)
#pragma unroll
        for (int j = 0; j < 4; j++) acc[i][j] = 0.f;

    for (int k0 = kbeg; k0 < kend; k0 += 32) {
#pragma unroll
        for (int i = 0; i < 4; i++)
            *(float4*)&As[lrow + 8 * i][lc4 * 4] =
                *(const float4*)(A + (size_t)(lrow + 8 * i) * lda + k0 + lc4 * 4);
#pragma unroll
        for (int i = 0; i < 4; i++)
            *(float4*)&Bs[lrow + 8 * i][lc4 * 4] =
                *(const float4*)(B + (size_t)(k0 + lrow + 8 * i) * ldb + n0 + lc4 * 4);
        __syncthreads();
#pragma unroll
        for (int kk = 0; kk < 32; kk++) {
            float a[4];
#pragma unroll
            for (int i = 0; i < 4; i++) a[i] = As[ty * 4 + i][kk];
            float4 bv = *(float4*)&Bs[kk][tx * 4];
#pragma unroll
            for (int i = 0; i < 4; i++) {
                acc[i][0] = fmaf(a[i], bv.x, acc[i][0]);
                acc[i][1] = fmaf(a[i], bv.y, acc[i][1]);
                acc[i][2] = fmaf(a[i], bv.z, acc[i][2]);
                acc[i][3] = fmaf(a[i], bv.w, acc[i][3]);
            }
        }
        __syncthreads();
    }
    float* dst = P + (size_t)ksi * 32 * N;
#pragma unroll
    for (int i = 0; i < 4; i++) {
        int m = ty * 4 + i;
#pragma unroll
        for (int j = 0; j < 4; j++)
            dst[(size_t)m * N + n0 + tx * 4 + j] = acc[i][j];
    }
}

__global__ void reduce2_kernel(float* d0, const float* P0, int ks0, int N0, const float* b0, int act0, int cnt0,
                               float* d1, const float* P1, int ks1, int N1, const float* b1, int act1, int cnt1)
{
    int i = blockIdx.x * 256 + threadIdx.x;
    float* d; const float* P; int ks, N; const float* bi; int act; int cnt;
    if (i < cnt0) { d=d0; P=P0; ks=ks0; N=N0; bi=b0; act=act0; cnt=cnt0; }
    else { i -= cnt0; d=d1; P=P1; ks=ks1; N=N1; bi=b1; act=act1; cnt=cnt1; }
    if (i >= cnt) return;
    float v = 0.f;
    for (int s = 0; s < ks; s++) v += P[(size_t)s * cnt + i];
    if (bi) v += bi[i % N];
    if (act == 1) v = tanhf(v);
    else if (act == 2) v = sigf(v);
    d[i] = v;
}

__global__ void avg_kernel(const float* __restrict__ img)
{
    int idx = blockIdx.x * blockDim.x + threadIdx.x;
    if (idx >= Bsz * (Dn / 4)) return;
    int b = idx >> 9;
    const float4* ip = (const float4*)img + (size_t)b * Pn * (Dn / 4) + (idx & 511);
    float4 s = make_float4(0.f, 0.f, 0.f, 0.f);
    for (int p = 0; p < Pn; p++) {
        float4 x = ip[(size_t)p * (Dn / 4)];
        s.x += x.x; s.y += x.y; s.z += x.z; s.w += x.w;
    }
    const float inv = 1.f / (float)Pn;
    s.x *= inv; s.y *= inv; s.z *= inv; s.w *= inv;
    ((float4*)g_avg)[idx] = s;
}

__global__ void emb_kernel(const int* __restrict__ caps, const float* __restrict__ E)
{
    int idx = blockIdx.x * blockDim.x + threadIdx.x;
    if (idx >= Bsz * Tn * Hn) return;
    int r = idx / Hn;
    int h = idx - r * Hn;
    int b = r / Tn, t = r - b * Tn;
    g_emb[idx] = E[(size_t)caps[b * 20 + t] * Hn + h];
}

// ==================== persistent step-loop kernel ====================
__device__ __forceinline__ void grid_barrier()
{
    __syncthreads();
    if (threadIdx.x == 0) {
        __threadfence();
        int gen = g_bargen;
        if (atomicAdd(&g_barcnt, 1) == NCTA - 1) {
            g_barcnt = 0;
            __threadfence();
            g_bargen = gen + 1;
        } else {
            while (g_bargen == gen) { __nanosleep(64); }
        }
        __threadfence();
    }
    __syncthreads();
}

// 32xN-tile GEMM over full k-range with 256 threads. A read via __ldcg.
__device__ __forceinline__ void gemm32_256(
    const float* __restrict__ A, int lda, int kbeg, int kend,
    const float* __restrict__ Bm, int ldb, int n0,
    const float* __restrict__ bias, int act,
    float* __restrict__ outp, int ldout,
    float* As, float* Bs, int tid)
{
    const int m = tid >> 3, n4 = (tid & 7) * 4;
    float4 acc = make_float4(0.f, 0.f, 0.f, 0.f);
    for (int k0 = kbeg; k0 < kend; k0 += 64) {
        {
            int r = tid >> 4, c = (tid & 15) * 4;
            *(float4*)&As[r * 68 + c] = __ldcg((const float4*)(A + (size_t)r * lda + k0 + c));
            r += 16;
            *(float4*)&As[r * 68 + c] = __ldcg((const float4*)(A + (size_t)r * lda + k0 + c));
        }
        {
            int r = tid >> 3, c = (tid & 7) * 4;
            *(float4*)&Bs[r * 32 + c] = *(const float4*)(Bm + (size_t)(k0 + r) * ldb + n0 + c);
            r += 32;
            *(float4*)&Bs[r * 32 + c] = *(const float4*)(Bm + (size_t)(k0 + r) * ldb + n0 + c);
        }
        __syncthreads();
#pragma unroll
        for (int kk = 0; kk < 64; kk++) {
            float a = As[m * 68 + kk];
            float4 b = *(float4*)&Bs[kk * 32 + n4];
            acc.x = fmaf(a, b.x, acc.x); acc.y = fmaf(a, b.y, acc.y);
            acc.z = fmaf(a, b.z, acc.z); acc.w = fmaf(a, b.w, acc.w);
        }
        __syncthreads();
    }
    if (bias) {
        const float4 bb = *(const float4*)(bias + n0 + n4);
        acc.x += bb.x; acc.y += bb.y; acc.z += bb.z; acc.w += bb.w;
    }
    if (act == 2) { acc.x = sigf(acc.x); acc.y = sigf(acc.y); acc.z = sigf(acc.z); acc.w = sigf(acc.w); }
    *(float4*)(outp + (size_t)m * ldout + n0 + n4) = acc;
}

__global__ __launch_bounds__(256)
void step_loop_kernel(const float* __restrict__ img,
                      const float* __restrict__ Wih, const float* __restrict__ Whh,
                      const float* __restrict__ bih, const float* __restrict__ bhh,
                      const float* __restrict__ W_fbeta, const float* __restrict__ b_fbeta,
                      const float* __restrict__ W_att_h, const float* __restrict__ b_att_h,
                      const float* __restrict__ v_att, const float* __restrict__ b_v_att,
                      float* __restrict__ out_alphas)
{
    const int cta = blockIdx.x, tid = threadIdx.x;
    const int w = tid >> 5, lane = tid & 31;
    __shared__ __align__(16) float SH[4224];

    const float* WihBot = Wih + (size_t)Hn * 4 * Hn;

    for (int t = 0; t < Tn; t++) {
        // ---- phase B: h-GEMMs (144 tasks) ----
        if (cta < 144) {
            if (cta < 16)
                gemm32_256(g_h, Hn, 0, Hn, W_att_h, Hn, cta * 32,
                           b_att_h, 0, g_hproj, Hn, SH, SH + 2176, tid);
            else if (cta < 80)
                gemm32_256(g_h, Hn, 0, Hn, W_fbeta, Dn, (cta - 16) * 32,
                           b_fbeta, 2, g_gate, Dn, SH, SH + 2176, tid);
            else
                gemm32_256(g_h, Hn, 0, Hn, Whh, 4 * Hn, (cta - 80) * 32,
                           nullptr, 0, g_pb, 4 * Hn, SH, SH + 2176, tid);
        }
        grid_barrier();

        // ---- phase C: scores (128 tasks: b x quarter) ----
        if (cta < 128) {
            int b = cta >> 2, q = cta & 3, p0 = q * 49;
            float* hp = SH;          // 512
            float* va = SH + 512;    // 512
            hp[tid]       = __ldcg(&g_hproj[b * Hn + tid]);
            hp[tid + 256] = __ldcg(&g_hproj[b * Hn + tid + 256]);
            va[tid]       = v_att[tid];
            va[tid + 256] = v_att[tid + 256];
            __syncthreads();
            const float bv = b_v_att[0];
            const float* ai = g_att_img + (size_t)b * Pn * Hn;
            for (int p = p0 + w; p < p0 + 49; p += 8) {
                const float* aip = ai + (size_t)p * Hn;
                float s = 0.f;
#pragma unroll
                for (int ii = 0; ii < Hn / 32; ii++) {
                    int hx = lane + 32 * ii;
                    float x = aip[hx] + hp[hx];
                    float th;
                    asm("tanh.approx.f32 %0, %1;" : "=f"(th) : "f"(x));
                    s = fmaf(th, va[hx], s);
                }
#pragma unroll
                for (int o = 16; o; o >>= 1) s += __shfl_down_sync(0xffffffffu, s, o);
                if (lane == 0) g_e[b * Pn + p] = s + bv;
            }
        }
        grid_barrier();

        // ---- phase D: softmax + context + gate -> xc (128 tasks: b x dslice) ----
        if (cta < 128) {
            int b = cta >> 2, sl = cta & 3;
            float*  ee   = SH;                        // 196
            float*  sred = SH + 200;                  // 8
            float4* redD = (float4*)(SH + 256);       // 2 x 128

            float v = (tid < Pn) ? __ldcg(&g_e[b * Pn + tid]) : -1e30f;
            float m = v;
#pragma unroll
            for (int o = 16; o; o >>= 1) m = fmaxf(m, __shfl_xor_sync(0xffffffffu, m, o));
            if (lane == 0) sred[w] = m;
            __syncthreads();
            if (tid < 32) {
                float mm = (tid < 8) ? sred[tid] : -1e30f;
#pragma unroll
                for (int o = 4; o; o >>= 1) mm = fmaxf(mm, __shfl_xor_sync(0xffffffffu, mm, o));
                if (tid == 0) sred[0] = mm;
            }
            __syncthreads();
            float ex = (tid < Pn) ? expf(v - sred[0]) : 0.f;
            __syncthreads();
            float s = ex;
#pragma unroll
            for (int o = 16; o; o >>= 1) s += __shfl_xor_sync(0xffffffffu, s, o);
            if (lane == 0) sred[w] = s;
            __syncthreads();
            if (tid < 32) {
                float ss = (tid < 8) ? sred[tid] : 0.f;
#pragma unroll
                for (int o = 4; o; o >>= 1) ss += __shfl_xor_sync(0xffffffffu, ss, o);
                if (tid == 0) sred[0] = ss;
            }
            __syncthreads();
            if (tid < Pn) {
                float a = ex / sred[0];
                ee[tid] = a;
                if (sl == 0) out_alphas[((size_t)b * Tn + t) * Pn + tid] = a;
            }
            __syncthreads();

            int ps = tid >> 7, dl = tid & 127;
            int d4 = sl * 128 + dl;
            const float4* ip = (const float4*)img + (size_t)b * Pn * (Dn / 4) + d4;
            float4 cx = make_float4(0.f, 0.f, 0.f, 0.f);
            for (int p = ps; p < Pn; p += 2) {
                float a = ee[p];
                float4 x = ip[(size_t)p * (Dn / 4)];
                cx.x = fmaf(a, x.x, cx.x); cx.y = fmaf(a, x.y, cx.y);
                cx.z = fmaf(a, x.z, cx.z); cx.w = fmaf(a, x.w, cx.w);
            }
            redD[ps * 128 + dl] = cx;
            __syncthreads();
            if (tid < 128) {
                float4 r0 = redD[tid], r1 = redD[128 + tid];
                float4 g4 = __ldcg((const float4*)g_gate + b * (Dn / 4) + d4);
                float4 o4;
                o4.x = (r0.x + r1.x) * g4.x; o4.y = (r0.y + r1.y) * g4.y;
                o4.z = (r0.z + r1.z) * g4.z; o4.w = (r0.w + r1.w) * g4.w;
                *((float4*)g_xc + b * (Dn / 4) + d4) = o4;
            }
        }
        grid_barrier();

        // ---- phase E: xc @ Wih_bot, ks=2 (128 tasks) ----
        if (cta < 128) {
            int nt = cta & 63, ksi = cta >> 6;
            gemm32_256(g_xc, Dn, ksi * 1024, ksi * 1024 + 1024,
                       WihBot, 4 * Hn, nt * 32, nullptr, 0,
                       g_pa + (size_t)ksi * Bsz * 4 * Hn, 4 * Hn, SH, SH + 2176, tid);
        }
        grid_barrier();

        // ---- phase F: LSTM pointwise (32 tasks) ----
        if (cta < 32) {
            int b = cta;
#pragma unroll
            for (int rep = 0; rep < 2; rep++) {
                int j = tid + rep * 256;
                float gv[4];
#pragma unroll
                for (int g = 0; g < 4; g++) {
                    int n = g * Hn + j;
                    int bn = b * 4 * Hn + n;
                    float vv = g_embW[(size_t)(b * Tn + t) * 4 * Hn + n] + bih[n] + bhh[n];
                    vv += __ldcg(&g_pa[bn]) + __ldcg(&g_pa[Bsz * 4 * Hn + bn]) + __ldcg(&g_pb[bn]);
                    gv[g] = vv;
                }
                float cold = __ldcg(&g_c[b * Hn + j]);
                float c = sigf(gv[1]) * cold + sigf(gv[0]) * tanhf(gv[2]);
                g_c[b * Hn + j] = c;
                float h = sigf(gv[3]) * tanhf(c);
                g_h[b * Hn + j] = h;
                size_t ro = (size_t)(t * Bsz + b) * Hn + j;
                g_hall[ro] = h;
                __nv_bfloat16 hh = __float2bfloat16(h);
                g_hallh[ro] = hh;
                g_halll[ro] = __float2bfloat16(h - __bfloat162float(hh));
            }
        }
        grid_barrier();
    }
}

// ================================================================================
extern "C" void kernel_launch(void* const* d_in, const int* in_sizes, int n_in,
                              void* d_out, int out_size)
{
    const float* img      = (const float*)d_in[0];
    const int*   caps     = (const int*)d_in[1];
    const float* Wih      = (const float*)d_in[2];
    const float* Whh      = (const float*)d_in[3];
    const float* bih      = (const float*)d_in[4];
    const float* bhh      = (const float*)d_in[5];
    const float* W_init_h = (const float*)d_in[6];
    const float* b_init_h = (const float*)d_in[7];
    const float* W_init_c = (const float*)d_in[8];
    const float* b_init_c = (const float*)d_in[9];
    const float* W_fbeta  = (const float*)d_in[10];
    const float* b_fbeta  = (const float*)d_in[11];
    const float* W_out    = (const float*)d_in[12];
    const float* b_out    = (const float*)d_in[13];
    const float* W_att_im = (const float*)d_in[14];
    const float* b_att_im = (const float*)d_in[15];
    const float* W_att_h  = (const float*)d_in[16];
    const float* b_att_h  = (const float*)d_in[17];
    const float* v_att    = (const float*)d_in[18];
    const float* b_v_att  = (const float*)d_in[19];
    const float* E        = (const float*)d_in[20];

    float* preds  = (float*)d_out;
    float* alphas = (float*)d_out + (size_t)Bsz * Tn * Vn;

    float *p_avg, *p_h, *p_c, *p_att, *p_emb, *p_embW, *p_pih, *p_pic;
    __nv_bfloat16 *p_imgh, *p_imgl, *p_watth, *p_wattl, *p_wouth, *p_woutl;
    __nv_bfloat16 *p_wihh, *p_wihl, *p_embh, *p_embl, *p_hallh, *p_halll;
    cudaGetSymbolAddress((void**)&p_avg,   g_avg);
    cudaGetSymbolAddress((void**)&p_h,     g_h);
    cudaGetSymbolAddress((void**)&p_c,     g_c);
    cudaGetSymbolAddress((void**)&p_att,   g_att_img);
    cudaGetSymbolAddress((void**)&p_emb,   g_emb);
    cudaGetSymbolAddress((void**)&p_embW,  g_embW);
    cudaGetSymbolAddress((void**)&p_pih,   g_pi_h);
    cudaGetSymbolAddress((void**)&p_pic,   g_pi_c);
    cudaGetSymbolAddress((void**)&p_imgh,  g_img_hi);
    cudaGetSymbolAddress((void**)&p_imgl,  g_img_lo);
    cudaGetSymbolAddress((void**)&p_watth, g_watt_hi);
    cudaGetSymbolAddress((void**)&p_wattl, g_watt_lo);
    cudaGetSymbolAddress((void**)&p_wouth, g_wout_hi);
    cudaGetSymbolAddress((void**)&p_woutl, g_wout_lo);
    cudaGetSymbolAddress((void**)&p_wihh,  g_wih_hi);
    cudaGetSymbolAddress((void**)&p_wihl,  g_wih_lo);
    cudaGetSymbolAddress((void**)&p_embh,  g_embh);
    cudaGetSymbolAddress((void**)&p_embl,  g_embl);
    cudaGetSymbolAddress((void**)&p_hallh, g_hallh);
    cudaGetSymbolAddress((void**)&p_halll, g_halll);

    cudaFuncSetAttribute(hmma_gemm<0>, cudaFuncAttributeMaxDynamicSharedMemorySize, HMMA_SMEM);
    cudaFuncSetAttribute(hmma_gemm<1>, cudaFuncAttributeMaxDynamicSharedMemorySize, HMMA_SMEM);

    // ---- setup (launch #4 = att hmma, profiled by ncu) ----
    conv_split<<<(Bsz * Pn * Dn) / 256, 256>>>(img, p_imgh, p_imgl, Bsz * Pn, Dn, Bsz * Pn);        // 1
    conv_splitT<<<dim3(Hn / 32, Dn / 32), dim3(32, 8)>>>(W_att_im, Hn, p_watth, p_wattl, Dn, Hn, Hn);// 2
    avg_kernel<<<64, 256>>>(img);                                                                    // 3
    hmma_gemm<0><<<dim3(Hn / 128, (Bsz * Pn) / 128), 256, HMMA_SMEM>>>(                              // 4
        p_imgh, p_imgl, p_watth, p_wattl, b_att_im, p_att, Bsz * Pn, Hn, Dn, Hn);
    conv_splitT<<<dim3(Vp / 32, Hn / 32), dim3(32, 8)>>>(W_out, Vn, p_wouth, p_woutl, Hn, Vn, Vp);
    conv_splitT<<<dim3(4 * Hn / 32, Hn / 32), dim3(32, 8)>>>(Wih, 4 * Hn, p_wihh, p_wihl, Hn, 4 * Hn, 4 * Hn);
    gemm_pass<<<256, 64>>>(p_avg, Dn, W_init_h, Hn, p_pih, Hn, Dn, 8, 16,
                           p_avg, Dn, W_init_c, Hn, p_pic, Hn, Dn, 8, 16);
    reduce2_kernel<<<128, 256>>>(p_h, p_pih, 8, Hn, b_init_h, 1, Bsz * Hn,
                                 p_c, p_pic, 8, Hn, b_init_c, 1, Bsz * Hn);
    emb_kernel<<<(Bsz * Tn * Hn) / 256, 256>>>(caps, E);
    conv_split<<<(Mp * Hn) / 256, 256>>>(p_emb, p_embh, p_embl, Mrows, Hn, Mp);
    hmma_gemm<0><<<dim3(4 * Hn / 128, Mp / 128), 256, HMMA_SMEM>>>(
        p_embh, p_embl, p_wihh, p_wihl, nullptr, p_embW, Mrows, 4 * Hn, Hn, 4 * Hn);
    pad_hall_kernel<<<((Mp - Mrows) * Hn + 255) / 256, 256>>>();

    // ---- all 19 recurrent steps in ONE persistent kernel ----
    step_loop_kernel<<<NCTA, 256>>>(img, Wih, Whh, bih, bhh, W_fbeta, b_fbeta,
                                    W_att_h, b_att_h, v_att, b_v_att, alphas);

    // ---- final: preds = h_all @ W_out + b_out ----
    hmma_gemm<1><<<dim3(Vp / 128, Mp / 128), 256, HMMA_SMEM>>>(
        p_hallh, p_halll, p_wouth, p_woutl, b_out, preds, Mrows, Vn, Hn, Vn);
}

// round 7
// speedup vs baseline: 1.6662x; 1.6662x over previous
#include <cuda_runtime.h>
#include <cuda_bf16.h>
#include <math.h>
#include <stdint.h>

#define Bsz 32
#define Pn  196
#define Dn  2048
#define Hn  512
#define Vn  30000
#define Tn  19
#define Vp  30080
#define Mrows 608
#define Mp  640

// ---------------- fp32 scratch ----------------
__device__ float g_avg[Bsz * Dn];
__device__ float g_h[Bsz * Hn];
__device__ float g_c[Bsz * Hn];
__device__ float g_hall[Tn * Bsz * Hn];          // rows = t*32+b
__device__ float g_att_img[Bsz * Pn * Hn];
__device__ float g_emb[Bsz * Tn * Hn];           // rows = b*19+t
__device__ float g_embW[Bsz * Tn * 4 * Hn];
__device__ float g_xc[Bsz * Dn];
__device__ float g_pp_h[4 * Bsz * Hn];           // hproj (ks=4)
__device__ float g_pp_g[4 * Bsz * Dn];           // fbeta (ks=4)
__device__ float g_pa[8 * Bsz * 4 * Hn];         // xc@Wih_bot (ks=8)
__device__ float g_pb[2 * Bsz * 4 * Hn];         // h@Whh (ks=2)
__device__ float g_pi_h[8 * Bsz * Hn];
__device__ float g_pi_c[8 * Bsz * Hn];

// ---------------- bf16 split scratch ----------------
__device__ __nv_bfloat16 g_img_hi[Bsz * Pn * Dn];
__device__ __nv_bfloat16 g_img_lo[Bsz * Pn * Dn];
__device__ __nv_bfloat16 g_watt_hi[Hn * Dn];
__device__ __nv_bfloat16 g_watt_lo[Hn * Dn];
__device__ __nv_bfloat16 g_wout_hi[Vp * Hn];
__device__ __nv_bfloat16 g_wout_lo[Vp * Hn];
__device__ __nv_bfloat16 g_wih_hi[4 * Hn * Hn];
__device__ __nv_bfloat16 g_wih_lo[4 * Hn * Hn];
__device__ __nv_bfloat16 g_embh[Mp * Hn];
__device__ __nv_bfloat16 g_embl[Mp * Hn];
__device__ __nv_bfloat16 g_hallh[Mp * Hn];
__device__ __nv_bfloat16 g_halll[Mp * Hn];

__device__ __forceinline__ float sigf(float x) { return 1.f / (1.f + expf(-x)); }

__device__ __forceinline__ uint32_t smem_u32(const void* p) {
    uint32_t a;
    asm("{ .reg .u64 t; cvta.to.shared.u64 t, %1; cvt.u32.u64 %0, t; }" : "=r"(a) : "l"(p));
    return a;
}
__device__ __forceinline__ void ldmx4(uint32_t* r, uint32_t addr) {
    asm volatile("ldmatrix.sync.aligned.m8n8.x4.shared.b16 {%0,%1,%2,%3}, [%4];"
                 : "=r"(r[0]), "=r"(r[1]), "=r"(r[2]), "=r"(r[3]) : "r"(addr));
}
__device__ __forceinline__ void mma16816(float* d, const uint32_t* a, const uint32_t* b) {
    asm volatile(
        "mma.sync.aligned.m16n8k16.row.col.f32.bf16.bf16.f32 "
        "{%0,%1,%2,%3}, {%4,%5,%6,%7}, {%8,%9}, {%0,%1,%2,%3};"
        : "+f"(d[0]), "+f"(d[1]), "+f"(d[2]), "+f"(d[3])
        : "r"(a[0]), "r"(a[1]), "r"(a[2]), "r"(a[3]), "r"(b[0]), "r"(b[1]));
}
#define CP16(s, g)  asm volatile("cp.async.cg.shared.global [%0], [%1], 16;" :: "r"(s), "l"(g))
#define CPCOMMIT()  asm volatile("cp.async.commit_group;" ::: "memory")
#define CPWAIT1()   asm volatile("cp.async.wait_group 1;" ::: "memory")
#define CPWAIT0()   asm volatile("cp.async.wait_group 0;" ::: "memory")

// ==================== split-bf16 HMMA GEMM: 2-stage, 2 CTAs/SM ====================
#define RSB 80
#define TSZ (128 * RSB)
#define STG (4 * TSZ)
#define HMMA_SMEM (2 * STG)      // 81920

template <int OUTMAP>
__global__ __launch_bounds__(256, 2)
void hmma_gemm(const __nv_bfloat16* __restrict__ Ahi, const __nv_bfloat16* __restrict__ Alo,
               const __nv_bfloat16* __restrict__ Bhi, const __nv_bfloat16* __restrict__ Blo,
               const float* __restrict__ bias, float* __restrict__ C,
               int M, int N, int K, int ldc)
{
    extern __shared__ char smc[];
    const uint32_t sb = smem_u32(smc);
    const int tid = threadIdx.x;
    const int lane = tid & 31, wid = tid >> 5;
    const int wm = wid & 1, wn = wid >> 1;
    const int m0 = blockIdx.y * 128, n0 = blockIdx.x * 128;

    int r0 = tid >> 2, c0 = tid & 3;
    int r1 = (tid + 256) >> 2, c1 = tid & 3;
    const __nv_bfloat16* base0[4] = {
        Ahi + (size_t)(m0 + r0) * K + c0 * 8,
        Alo + (size_t)(m0 + r0) * K + c0 * 8,
        Bhi + (size_t)(n0 + r0) * K + c0 * 8,
        Blo + (size_t)(n0 + r0) * K + c0 * 8 };
    const __nv_bfloat16* base1[4] = {
        Ahi + (size_t)(m0 + r1) * K + c1 * 8,
        Alo + (size_t)(m0 + r1) * K + c1 * 8,
        Bhi + (size_t)(n0 + r1) * K + c1 * 8,
        Blo + (size_t)(n0 + r1) * K + c1 * 8 };
    const uint32_t so0 = (uint32_t)(r0 * RSB + c0 * 16);
    const uint32_t so1 = (uint32_t)(r1 * RSB + c1 * 16);

    const int arow = (lane & 7) | (((lane >> 3) & 1) << 3);
    const int akh  = lane >> 4;
    const int brow = (lane & 7) + ((lane >> 4) << 3);
    const int bkh  = (lane >> 3) & 1;

    float acc[4][4][4];
#pragma unroll
    for (int i = 0; i < 4; i++)
#pragma unroll
        for (int j = 0; j < 4; j++)
#pragma unroll
            for (int e = 0; e < 4; e++) acc[i][j][e] = 0.f;

    const int nit = K / 32;

#pragma unroll
    for (int pi = 0; pi < 2; pi++) {
        uint32_t dst = sb + pi * STG;
        int kof = pi * 32;
#pragma unroll
        for (int tno = 0; tno < 4; tno++) {
            CP16(dst + tno * TSZ + so0, base0[tno] + kof);
            CP16(dst + tno * TSZ + so1, base1[tno] + kof);
        }
        CPCOMMIT();
    }

    for (int it = 0; it < nit; it++) {
        if (it + 1 < nit) { CPWAIT1(); } else { CPWAIT0(); }
        __syncthreads();

        const uint32_t stb = sb + (it & 1) * STG;
#pragma unroll
        for (int ks = 0; ks < 2; ks++) {
            uint32_t ah[4][4], al[4][4], bh[4][2], bl[4][2];
#pragma unroll
            for (int mt = 0; mt < 4; mt++) {
                uint32_t ra = (uint32_t)((wm * 64 + mt * 16 + arow) * RSB + ks * 32 + akh * 16);
                ldmx4(ah[mt], stb + 0 * TSZ + ra);
                ldmx4(al[mt], stb + 1 * TSZ + ra);
            }
#pragma unroll
            for (int g = 0; g < 2; g++) {
                uint32_t rb = (uint32_t)((wn * 32 + g * 16 + brow) * RSB + ks * 32 + bkh * 16);
                uint32_t t0[4], t1[4];
                ldmx4(t0, stb + 2 * TSZ + rb);
                ldmx4(t1, stb + 3 * TSZ + rb);
                bh[g * 2][0] = t0[0]; bh[g * 2][1] = t0[1];
                bh[g * 2 + 1][0] = t0[2]; bh[g * 2 + 1][1] = t0[3];
                bl[g * 2][0] = t1[0]; bl[g * 2][1] = t1[1];
                bl[g * 2 + 1][0] = t1[2]; bl[g * 2 + 1][1] = t1[3];
            }
#pragma unroll
            for (int mt = 0; mt < 4; mt++)
#pragma unroll
                for (int nt = 0; nt < 4; nt++) {
                    mma16816(acc[mt][nt], ah[mt], bh[nt]);
                    mma16816(acc[mt][nt], ah[mt], bl[nt]);
                    mma16816(acc[mt][nt], al[mt], bh[nt]);
                }
        }
        __syncthreads();

        if (it + 2 < nit) {
            uint32_t dst = sb + (it & 1) * STG;
            int kof = (it + 2) * 32;
#pragma unroll
            for (int tno = 0; tno < 4; tno++) {
                CP16(dst + tno * TSZ + so0, base0[tno] + kof);
                CP16(dst + tno * TSZ + so1, base1[tno] + kof);
            }
            CPCOMMIT();
        }
    }

#pragma unroll
    for (int mt = 0; mt < 4; mt++) {
#pragma unroll
        for (int half = 0; half < 2; half++) {
            int r = m0 + wm * 64 + mt * 16 + (lane >> 2) + half * 8;
            bool rowok; float* Crow;
            if (OUTMAP) {
                int ob = r & 31, ot = r >> 5;
                rowok = (ot < Tn);
                Crow = C + (size_t)(ob * Tn + ot) * ldc;
            } else {
                rowok = (r < M);
                Crow = C + (size_t)r * ldc;
            }
            if (!rowok) continue;
#pragma unroll
            for (int nt = 0; nt < 4; nt++) {
                int n = n0 + wn * 32 + nt * 8 + (lane & 3) * 2;
                if (n + 1 < N) {
                    float v0 = acc[mt][nt][half * 2 + 0];
                    float v1 = acc[mt][nt][half * 2 + 1];
                    if (bias) { v0 += bias[n]; v1 += bias[n + 1]; }
                    *(float2*)(Crow + n) = make_float2(v0, v1);
                } else if (n < N) {
                    float v0 = acc[mt][nt][half * 2 + 0];
                    if (bias) v0 += bias[n];
                    Crow[n] = v0;
                }
            }
        }
    }
}

// ==================== conversions ====================
__global__ void conv_split(const float* __restrict__ src, __nv_bfloat16* __restrict__ hi,
                           __nv_bfloat16* __restrict__ lo, int M, int K, int Mpad)
{
    int idx = blockIdx.x * 256 + threadIdx.x;
    if (idx >= Mpad * K) return;
    float v;
    if (M == Mpad) {
        v = src[idx];
    } else {
        int r = idx / K;
        v = (r < M) ? src[idx] : 0.f;
    }
    __nv_bfloat16 h = __float2bfloat16(v);
    hi[idx] = h;
    lo[idx] = __float2bfloat16(v - __bfloat162float(h));
}

__global__ void conv_splitT(const float* __restrict__ src, int ldsrc,
                            __nv_bfloat16* __restrict__ hi, __nv_bfloat16* __restrict__ lo,
                            int K, int N, int Npad)
{
    __shared__ float tile[32][33];
    int n0 = blockIdx.x * 32, k0 = blockIdx.y * 32;
    int tx = threadIdx.x, ty = threadIdx.y;
#pragma unroll
    for (int i = 0; i < 32; i += 8) {
        int n = n0 + tx;
        tile[ty + i][tx] = (n < N) ? src[(size_t)(k0 + ty + i) * ldsrc + n] : 0.f;
    }
    __syncthreads();
#pragma unroll
    for (int i = 0; i < 32; i += 8) {
        int n = n0 + ty + i, k = k0 + tx;
        if (n < Npad) {
            float v = tile[tx][ty + i];
            __nv_bfloat16 h = __float2bfloat16(v);
            hi[(size_t)n * K + k] = h;
            lo[(size_t)n * K + k] = __float2bfloat16(v - __bfloat162float(h));
        }
    }
}

__global__ void pad_hall_kernel()
{
    int idx = blockIdx.x * 256 + threadIdx.x;
    if (idx >= (Mp - Mrows) * Hn) return;
    g_hallh[Mrows * Hn + idx] = __float2bfloat16(0.f);
    g_halll[Mrows * Hn + idx] = __float2bfloat16(0.f);
}

// ==================== small GEMM pass (fp32, split-K) ====================
__global__ __launch_bounds__(64)
void gemm_pass(const float* A0, int lda0, const float* B0, int ldb0, float* P0, int N0, int K0, int ks0, int nt0,
               const float* A1, int lda1, const float* B1, int ldb1, float* P1, int N1, int K1, int ks1, int nt1)
{
    const float* A; const float* B; float* P;
    int N, K, ks, nt, lda, ldb;
    int id = blockIdx.x;
    int blocks0 = nt0 * ks0;
    if (id < blocks0) { A=A0; B=B0; P=P0; N=N0; K=K0; ks=ks0; nt=nt0; lda=lda0; ldb=ldb0; }
    else { id -= blocks0; A=A1; B=B1; P=P1; N=N1; K=K1; ks=ks1; nt=nt1; lda=lda1; ldb=ldb1; }

    int ntile = id % nt;
    int ksi   = id / nt;
    int kLen  = K / ks;
    int kbeg  = ksi * kLen, kend = kbeg + kLen;
    int n0    = ntile * 32;

    __shared__ float As[32][36];
    __shared__ float Bs[32][32];
    const int tid = threadIdx.x;
    const int tx = tid & 7, ty = tid >> 3;
    const int lrow = tid >> 3, lc4 = tid & 7;

    float acc[4][4];
#pragma unroll
    for (int i = 0; i < 4; i++)
#pragma unroll
        for (int j = 0; j < 4; j++) acc[i][j] = 0.f;

    for (int k0 = kbeg; k0 < kend; k0 += 32) {
#pragma unroll
        for (int i = 0; i < 4; i++)
            *(float4*)&As[lrow + 8 * i][lc4 * 4] =
                *(const float4*)(A + (size_t)(lrow + 8 * i) * lda + k0 + lc4 * 4);
#pragma unroll
        for (int i = 0; i < 4; i++)
            *(float4*)&Bs[lrow + 8 * i][lc4 * 4] =
                *(const float4*)(B + (size_t)(k0 + lrow + 8 * i) * ldb + n0 + lc4 * 4);
        __syncthreads();
#pragma unroll
        for (int kk = 0; kk < 32; kk++) {
            float a[4];
#pragma unroll
            for (int i = 0; i < 4; i++) a[i] = As[ty * 4 + i][kk];
            float4 bv = *(float4*)&Bs[kk][tx * 4];
#pragma unroll
            for (int i = 0; i < 4; i++) {
                acc[i][0] = fmaf(a[i], bv.x, acc[i][0]);
                acc[i][1] = fmaf(a[i], bv.y, acc[i][1]);
                acc[i][2] = fmaf(a[i], bv.z, acc[i][2]);
                acc[i][3] = fmaf(a[i], bv.w, acc[i][3]);
            }
        }
        __syncthreads();
    }
    float* dst = P + (size_t)ksi * 32 * N;
#pragma unroll
    for (int i = 0; i < 4; i++) {
        int m = ty * 4 + i;
#pragma unroll
        for (int j = 0; j < 4; j++)
            dst[(size_t)m * N + n0 + tx * 4 + j] = acc[i][j];
    }
}

// ==================== init reduce (used once) ====================
__global__ void reduce2_kernel(float* d0, const float* P0, int ks0, int N0, const float* b0, int act0, int cnt0,
                               float* d1, const float* P1, int ks1, int N1, const float* b1, int act1, int cnt1)
{
    int i = blockIdx.x * 256 + threadIdx.x;
    float* d; const float* P; int ks, N; const float* bi; int act; int cnt;
    if (i < cnt0) { d=d0; P=P0; ks=ks0; N=N0; bi=b0; act=act0; cnt=cnt0; }
    else { i -= cnt0; d=d1; P=P1; ks=ks1; N=N1; bi=b1; act=act1; cnt=cnt1; }
    if (i >= cnt) return;
    float v = 0.f;
    for (int s = 0; s < ks; s++) v += P[(size_t)s * cnt + i];
    if (bi) v += bi[i % N];
    if (act == 1) v = tanhf(v);
    else if (act == 2) v = sigf(v);
    d[i] = v;
}

// ==================== misc ====================
__global__ void avg_kernel(const float* __restrict__ img)
{
    int idx = blockIdx.x * blockDim.x + threadIdx.x;
    if (idx >= Bsz * (Dn / 4)) return;
    int b = idx >> 9;
    const float4* ip = (const float4*)img + (size_t)b * Pn * (Dn / 4) + (idx & 511);
    float4 s = make_float4(0.f, 0.f, 0.f, 0.f);
    for (int p = 0; p < Pn; p++) {
        float4 x = ip[(size_t)p * (Dn / 4)];
        s.x += x.x; s.y += x.y; s.z += x.z; s.w += x.w;
    }
    const float inv = 1.f / (float)Pn;
    s.x *= inv; s.y *= inv; s.z *= inv; s.w *= inv;
    ((float4*)g_avg)[idx] = s;
}

__global__ void emb_kernel(const int* __restrict__ caps, const float* __restrict__ E)
{
    int idx = blockIdx.x * blockDim.x + threadIdx.x;
    if (idx >= Bsz * Tn * Hn) return;
    int r = idx / Hn;
    int h = idx - r * Hn;
    int b = r / Tn, t = r - b * Tn;
    g_emb[idx] = E[(size_t)caps[b * 20 + t] * Hn + h];
}

// ==================== fused attention step v2: one block per b, 1024 threads ====
__global__ __launch_bounds__(1024)
void attctx_kernel(const float* __restrict__ img,
                   const float* __restrict__ v_att, const float* __restrict__ b_v_att,
                   const float* __restrict__ b_att_h, const float* __restrict__ b_fbeta,
                   float* __restrict__ out_alphas, int t)
{
    const int b = blockIdx.x, tid = threadIdx.x;
    const int w = tid >> 5, lane = tid & 31;
    __shared__ float hp[Hn];
    __shared__ float va[Hn];
    __shared__ float ee[Pn];
    __shared__ float sred[8];
    __shared__ __align__(16) float4 redD[2 * (Dn / 4)];   // 16KB

    // 1. hproj reduce + bias
    if (tid < Hn) {
        float v = b_att_h[tid];
#pragma unroll
        for (int s = 0; s < 4; s++) v += g_pp_h[s * Bsz * Hn + b * Hn + tid];
        hp[tid] = v;
        va[tid] = v_att[tid];
    }
    __syncthreads();

    // 2. scores: 32 warps over 196 p
    const float* ai = g_att_img + (size_t)b * Pn * Hn;
    const float bv0 = b_v_att[0];
    for (int p = w; p < Pn; p += 32) {
        const float* aip = ai + (size_t)p * Hn;
        float s = 0.f;
#pragma unroll
        for (int ii = 0; ii < Hn / 32; ii++) {
            int hx = lane + 32 * ii;
            float x = aip[hx] + hp[hx];
            float th;
            asm("tanh.approx.f32 %0, %1;" : "=f"(th) : "f"(x));
            s = fmaf(th, va[hx], s);
        }
#pragma unroll
        for (int o = 16; o; o >>= 1) s += __shfl_down_sync(0xffffffffu, s, o);
        if (lane == 0) ee[p] = s + bv0;
    }
    __syncthreads();

    // 3. softmax over P=196 (warps 0..7 only for reductions)
    float v = (tid < Pn) ? ee[tid] : -1e30f;
    if (tid < 256) {
        float m = v;
#pragma unroll
        for (int o = 16; o; o >>= 1) m = fmaxf(m, __shfl_xor_sync(0xffffffffu, m, o));
        if (lane == 0) sred[w] = m;
    }
    __syncthreads();
    if (tid < 32) {
        float mm = (tid < 8) ? sred[tid] : -1e30f;
#pragma unroll
        for (int o = 4; o; o >>= 1) mm = fmaxf(mm, __shfl_xor_sync(0xffffffffu, mm, o));
        if (tid == 0) sred[0] = mm;
    }
    __syncthreads();
    float exv = (tid < Pn) ? expf(v - sred[0]) : 0.f;
    __syncthreads();
    if (tid < 256) {
        float s = exv;
#pragma unroll
        for (int o = 16; o; o >>= 1) s += __shfl_xor_sync(0xffffffffu, s, o);
        if (lane == 0) sred[w] = s;
    }
    __syncthreads();
    if (tid < 32) {
        float ss = (tid < 8) ? sred[tid] : 0.f;
#pragma unroll
        for (int o = 4; o; o >>= 1) ss += __shfl_xor_sync(0xffffffffu, ss, o);
        if (tid == 0) sred[0] = ss;
    }
    __syncthreads();
    if (tid < Pn) {
        float a = exv / sred[0];
        ee[tid] = a;
        out_alphas[((size_t)b * Tn + t) * Pn + tid] = a;
    }
    __syncthreads();

    // 4. context: 2-way p-split, unroll-8 for MLP; then gate -> xc
    const int ps = tid >> 9;          // 0/1
    const int d4 = tid & 511;
    const float4* ip = (const float4*)img + (size_t)b * Pn * (Dn / 4) + d4;
    float4 cx = make_float4(0.f, 0.f, 0.f, 0.f);
#pragma unroll 8
    for (int p = ps; p < Pn; p += 2) {
        float a = ee[p];
        float4 x = ip[(size_t)p * (Dn / 4)];
        cx.x = fmaf(a, x.x, cx.x); cx.y = fmaf(a, x.y, cx.y);
        cx.z = fmaf(a, x.z, cx.z); cx.w = fmaf(a, x.w, cx.w);
    }
    redD[ps * (Dn / 4) + d4] = cx;
    __syncthreads();
    if (tid < Dn / 4) {
        float4 r0 = redD[tid], r1 = redD[(Dn / 4) + tid];
        float4 gb = *(const float4*)(b_fbeta + tid * 4);
#pragma unroll
        for (int sp = 0; sp < 4; sp++) {
            float4 pv = ((const float4*)g_pp_g)[sp * (Bsz * Dn / 4) + b * (Dn / 4) + tid];
            gb.x += pv.x; gb.y += pv.y; gb.z += pv.z; gb.w += pv.w;
        }
        float4 o4;
        o4.x = (r0.x + r1.x) * sigf(gb.x);
        o4.y = (r0.y + r1.y) * sigf(gb.y);
        o4.z = (r0.z + r1.z) * sigf(gb.z);
        o4.w = (r0.w + r1.w) * sigf(gb.w);
        ((float4*)g_xc)[b * (Dn / 4) + tid] = o4;
    }
}

// LSTM pointwise: sum 8 pa + 2 pb partials + embW + biases; writes h + bf16 split
__global__ void lstm_kernel(const float* __restrict__ bih, const float* __restrict__ bhh, int t)
{
    int idx = blockIdx.x * blockDim.x + threadIdx.x;
    if (idx >= Bsz * Hn) return;
    int b = idx >> 9;
    int j = idx & 511;
    int rowE = (b * Tn + t) * 4 * Hn;
    int rowP = b * 4 * Hn;

    float gv[4];
#pragma unroll
    for (int g = 0; g < 4; g++) {
        int n = g * Hn + j;
        float v = g_embW[rowE + n] + bih[n] + bhh[n];
#pragma unroll
        for (int s = 0; s < 8; s++) v += g_pa[s * Bsz * 4 * Hn + rowP + n];
        v += g_pb[rowP + n] + g_pb[Bsz * 4 * Hn + rowP + n];
        gv[g] = v;
    }
    float c = sigf(gv[1]) * g_c[idx] + sigf(gv[0]) * tanhf(gv[2]);
    g_c[idx] = c;
    float h = sigf(gv[3]) * tanhf(c);
    g_h[idx] = h;
    size_t ro = (size_t)(t * Bsz + b) * Hn + j;
    g_hall[ro] = h;
    __nv_bfloat16 hh = __float2bfloat16(h);
    g_hallh[ro] = hh;
    g_halll[ro] = __float2bfloat16(h - __bfloat162float(hh));
}

// ================================================================================
extern "C" void kernel_launch(void* const* d_in, const int* in_sizes, int n_in,
                              void* d_out, int out_size)
{
    const float* img      = (const float*)d_in[0];
    const int*   caps     = (const int*)d_in[1];
    const float* Wih      = (const float*)d_in[2];
    const float* Whh      = (const float*)d_in[3];
    const float* bih      = (const float*)d_in[4];
    const float* bhh      = (const float*)d_in[5];
    const float* W_init_h = (const float*)d_in[6];
    const float* b_init_h = (const float*)d_in[7];
    const float* W_init_c = (const float*)d_in[8];
    const float* b_init_c = (const float*)d_in[9];
    const float* W_fbeta  = (const float*)d_in[10];
    const float* b_fbeta  = (const float*)d_in[11];
    const float* W_out    = (const float*)d_in[12];
    const float* b_out    = (const float*)d_in[13];
    const float* W_att_im = (const float*)d_in[14];
    const float* b_att_im = (const float*)d_in[15];
    const float* W_att_h  = (const float*)d_in[16];
    const float* b_att_h  = (const float*)d_in[17];
    const float* v_att    = (const float*)d_in[18];
    const float* b_v_att  = (const float*)d_in[19];
    const float* E        = (const float*)d_in[20];

    float* preds  = (float*)d_out;
    float* alphas = (float*)d_out + (size_t)Bsz * Tn * Vn;

    float *p_avg, *p_h, *p_c, *p_att, *p_emb, *p_embW, *p_xc, *p_pph, *p_ppg;
    float *p_pa, *p_pb, *p_pih, *p_pic;
    __nv_bfloat16 *p_imgh, *p_imgl, *p_watth, *p_wattl, *p_wouth, *p_woutl;
    __nv_bfloat16 *p_wihh, *p_wihl, *p_embh, *p_embl, *p_hallh, *p_halll;
    cudaGetSymbolAddress((void**)&p_avg,   g_avg);
    cudaGetSymbolAddress((void**)&p_h,     g_h);
    cudaGetSymbolAddress((void**)&p_c,     g_c);
    cudaGetSymbolAddress((void**)&p_att,   g_att_img);
    cudaGetSymbolAddress((void**)&p_emb,   g_emb);
    cudaGetSymbolAddress((void**)&p_embW,  g_embW);
    cudaGetSymbolAddress((void**)&p_xc,    g_xc);
    cudaGetSymbolAddress((void**)&p_pph,   g_pp_h);
    cudaGetSymbolAddress((void**)&p_ppg,   g_pp_g);
    cudaGetSymbolAddress((void**)&p_pa,    g_pa);
    cudaGetSymbolAddress((void**)&p_pb,    g_pb);
    cudaGetSymbolAddress((void**)&p_pih,   g_pi_h);
    cudaGetSymbolAddress((void**)&p_pic,   g_pi_c);
    cudaGetSymbolAddress((void**)&p_imgh,  g_img_hi);
    cudaGetSymbolAddress((void**)&p_imgl,  g_img_lo);
    cudaGetSymbolAddress((void**)&p_watth, g_watt_hi);
    cudaGetSymbolAddress((void**)&p_wattl, g_watt_lo);
    cudaGetSymbolAddress((void**)&p_wouth, g_wout_hi);
    cudaGetSymbolAddress((void**)&p_woutl, g_wout_lo);
    cudaGetSymbolAddress((void**)&p_wihh,  g_wih_hi);
    cudaGetSymbolAddress((void**)&p_wihl,  g_wih_lo);
    cudaGetSymbolAddress((void**)&p_embh,  g_embh);
    cudaGetSymbolAddress((void**)&p_embl,  g_embl);
    cudaGetSymbolAddress((void**)&p_hallh, g_hallh);
    cudaGetSymbolAddress((void**)&p_halll, g_halll);

    cudaFuncSetAttribute(hmma_gemm<0>, cudaFuncAttributeMaxDynamicSharedMemorySize, HMMA_SMEM);
    cudaFuncSetAttribute(hmma_gemm<1>, cudaFuncAttributeMaxDynamicSharedMemorySize, HMMA_SMEM);

    // ---- setup (launch index 3 (0-based) = att hmma -> ncu slot) ----
    conv_split<<<(Bsz * Pn * Dn) / 256, 256>>>(img, p_imgh, p_imgl, Bsz * Pn, Dn, Bsz * Pn);          // 0
    conv_splitT<<<dim3(Hn / 32, Dn / 32), dim3(32, 8)>>>(W_att_im, Hn, p_watth, p_wattl, Dn, Hn, Hn); // 1
    avg_kernel<<<64, 256>>>(img);                                                                     // 2
    hmma_gemm<0><<<dim3(Hn / 128, (Bsz * Pn) / 128), 256, HMMA_SMEM>>>(                               // 3
        p_imgh, p_imgl, p_watth, p_wattl, b_att_im, p_att, Bsz * Pn, Hn, Dn, Hn);
    conv_splitT<<<dim3(Vp / 32, Hn / 32), dim3(32, 8)>>>(W_out, Vn, p_wouth, p_woutl, Hn, Vn, Vp);
    conv_splitT<<<dim3(4 * Hn / 32, Hn / 32), dim3(32, 8)>>>(Wih, 4 * Hn, p_wihh, p_wihl, Hn, 4 * Hn, 4 * Hn);
    gemm_pass<<<256, 64>>>(p_avg, Dn, W_init_h, Hn, p_pih, Hn, Dn, 8, 16,
                           p_avg, Dn, W_init_c, Hn, p_pic, Hn, Dn, 8, 16);
    reduce2_kernel<<<128, 256>>>(p_h, p_pih, 8, Hn, b_init_h, 1, Bsz * Hn,
                                 p_c, p_pic, 8, Hn, b_init_c, 1, Bsz * Hn);
    emb_kernel<<<(Bsz * Tn * Hn) / 256, 256>>>(caps, E);
    conv_split<<<(Mp * Hn) / 256, 256>>>(p_emb, p_embh, p_embl, Mrows, Hn, Mp);
    hmma_gemm<0><<<dim3(4 * Hn / 128, Mp / 128), 256, HMMA_SMEM>>>(
        p_embh, p_embl, p_wihh, p_wihl, nullptr, p_embW, Mrows, 4 * Hn, Hn, 4 * Hn);
    pad_hall_kernel<<<((Mp - Mrows) * Hn + 255) / 256, 256>>>();

    // ---- recurrent steps: 4 kernels/step ----
    for (int t = 0; t < Tn; t++) {
        gemm_pass<<<64 + 256, 64>>>(p_h, Hn, W_att_h, Hn, p_pph, Hn, Hn, 4, 16,
                                    p_h, Hn, W_fbeta, Dn, p_ppg, Dn, Hn, 4, 64);
        attctx_kernel<<<Bsz, 1024>>>(img, v_att, b_v_att, b_att_h, b_fbeta, alphas, t);
        gemm_pass<<<512 + 128, 64>>>(p_xc, Dn, Wih + (size_t)Hn * 4 * Hn, 4 * Hn, p_pa, 4 * Hn, Dn, 8, 64,
                                     p_h,  Hn, Whh,                        4 * Hn, p_pb, 4 * Hn, Hn, 2, 64);
        lstm_kernel<<<(Bsz * Hn) / 256, 256>>>(bih, bhh, t);
    }

    // ---- final: preds = h_all @ W_out + b_out ----
    hmma_gemm<1><<<dim3(Vp / 128, Mp / 128), 256, HMMA_SMEM>>>(
        p_hallh, p_halll, p_wouth, p_woutl, b_out, preds, Mrows, Vn, Hn, Vn);
}